// round 14
// baseline (speedup 1.0000x reference)
#include <cuda_runtime.h>
#include <cuda_fp16.h>
#include <cstdint>

#define DIM     64
#define KMAX    1024
#define TM      512          // rows per CTA
#define THREADS 512          // 16 warps x 2 m-tiles = 32 rows per warp

// ---------------- device globals (prep results) ----------------
__device__ float g_c2[KMAX];
__device__ unsigned int g_cmaxU;   // asuint(max ||c_k||), positive-float monotone
// fragment-ordered fp16 (x512) codebook image: for each n-tile (8 codes) the exact
// 8 B-fragment regs x 32 lanes the MMA needs. uint4 index = nt*64 + half*32 + lane.
__device__ __align__(16) uint4 g_cbFrag[(KMAX / 8) * 64];

// ---------------- smem layout (byte offsets) ----------------
#define OFF_A     0          // 512*128 = 65536 (fp16 swizzled A staging)
#define OFF_C2    65536      // 4096   (raw c2, exact phase)
#define OFF_C2B   69632      // 4096   (c2 + 0.25 bias, scan phase)
#define OFF_R2    73728      // 2048
#define OFF_M1    75776      // 2048
#define OFF_M2    77824      // 2048
#define OFF_FLAG  79872      // 2048
#define OFF_NF    81920      // 16
#define SMEM_DYN  81936

#define BIAS 0.25f
#define DEQ  (-0.00390625f)   // -2^-8 : undoes B x512 and applies the -2 factor

__device__ __forceinline__ uint32_t smem_u32(const void* p) {
    uint32_t a;
    asm("{ .reg .u64 t; cvta.to.shared.u64 t, %1; cvt.u32.u64 %0, t; }"
        : "=r"(a) : "l"(p));
    return a;
}

// ---------------- prep: c2 (R1-exact) + fp16 fragment codebook (x512) + Cmax ----------------
__global__ void prep_kernel(const float* __restrict__ cb, int K) {
    int k = blockIdx.x * blockDim.x + threadIdx.x;
    if (k >= K) return;
    const float4* row = reinterpret_cast<const float4*>(cb + (size_t)k * DIM);
    float vals[DIM];
    float p0 = 0.f, p1 = 0.f, p2 = 0.f, p3 = 0.f;
#pragma unroll
    for (int j = 0; j < 16; j += 4) {
        float4 a = row[j + 0];
        float4 b = row[j + 1];
        float4 c = row[j + 2];
        float4 d = row[j + 3];
        p0 += a.x * a.x + a.y * a.y + a.z * a.z + a.w * a.w;
        p1 += b.x * b.x + b.y * b.y + b.z * b.z + b.w * b.w;
        p2 += c.x * c.x + c.y * c.y + c.z * c.z + c.w * c.w;
        p3 += d.x * d.x + d.y * d.y + d.z * d.z + d.w * d.w;
        vals[4*(j+0)+0]=a.x; vals[4*(j+0)+1]=a.y; vals[4*(j+0)+2]=a.z; vals[4*(j+0)+3]=a.w;
        vals[4*(j+1)+0]=b.x; vals[4*(j+1)+1]=b.y; vals[4*(j+1)+2]=b.z; vals[4*(j+1)+3]=b.w;
        vals[4*(j+2)+0]=c.x; vals[4*(j+2)+1]=c.y; vals[4*(j+2)+2]=c.z; vals[4*(j+2)+3]=c.w;
        vals[4*(j+3)+0]=d.x; vals[4*(j+3)+1]=d.y; vals[4*(j+3)+2]=d.z; vals[4*(j+3)+3]=d.w;
    }
    float c2 = (p0 + p1) + (p2 + p3);
    g_c2[k] = c2;
    atomicMax(&g_cmaxU, __float_as_uint(sqrtf(c2)));

    // Fragment image: lane l=4*i+q (i = code-in-tile) receives in b-reg j the fp16
    // pair (k-dims 8j+2q, 8j+2q+1), scaled x512.
    const int nt = k >> 3, i = k & 7;
    unsigned int* frag = reinterpret_cast<unsigned int*>(g_cbFrag) + nt * 256;
#pragma unroll
    for (int j = 0; j < 8; j++) {
#pragma unroll
        for (int q = 0; q < 4; q++) {
            __half2 pr = __floats2half2_rn(vals[8 * j + 2 * q]     * 512.0f,
                                           vals[8 * j + 2 * q + 1] * 512.0f);
            frag[(j >> 2) * 128 + (4 * i + q) * 4 + (j & 3)] =
                *reinterpret_cast<unsigned int*>(&pr);
        }
    }
}

// ---------------- inner-step macros ----------------
#define MMAF16(d0, d1, d2, d3, ar, b0r, b1r)                                       \
    asm volatile(                                                                  \
        "mma.sync.aligned.m16n8k16.row.col.f32.f16.f16.f32 "                       \
        "{%0,%1,%2,%3}, {%4,%5,%6,%7}, {%8,%9}, {%0,%1,%2,%3};"                    \
        : "+f"(d0), "+f"(d1), "+f"(d2), "+f"(d3)                                   \
        : "r"((ar)[0]), "r"((ar)[1]), "r"((ar)[2]), "r"((ar)[3]),                  \
          "r"(b0r), "r"(b1r))

// insert packed value v into sorted pair (M1x,M2x)
#define MIN2(M1x, M2x, v) do {                                                     \
    unsigned int t1 = umax(M1x, (v));                                              \
    M1x = umin(M1x, (v));                                                          \
    M2x = umin(M2x, t1);                                                           \
} while (0)

// merge other sorted pair (o1<=o2) into (M1x,M2x)
#define MERGE2(M1x, M2x, o1, o2) do {                                              \
    unsigned int hi = umax(M1x, (o1));                                             \
    M1x = umin(M1x, (o1));                                                         \
    M2x = umin(hi, umin(M2x, (o2)));                                               \
} while (0)

#define PACKV(sv, col) ((__float_as_uint(sv) & 0xFFFFFC00u) | (unsigned int)(col))

// one m-tile (4 MMAs, 2 independent chains) -> 4 s-values -> two min2 slots
#define MT_STEP(amt, P1, P2, Q1, Q2) do {                                          \
    float e0 = 0.f, e1 = 0.f, e2 = 0.f, e3 = 0.f;                                  \
    float f0 = 0.f, f1 = 0.f, f2 = 0.f, f3 = 0.f;                                  \
    MMAF16(e0, e1, e2, e3, (amt)[0], c0.x, c0.y);                                  \
    MMAF16(f0, f1, f2, f3, (amt)[2], c1.x, c1.y);                                  \
    MMAF16(e0, e1, e2, e3, (amt)[1], c0.z, c0.w);                                  \
    MMAF16(f0, f1, f2, f3, (amt)[3], c1.z, c1.w);                                  \
    float s;                                                                       \
    s = __fmaf_rn(__fadd_rn(e0, f0), DEQ, c2v.x); MIN2(P1, P2, PACKV(s, col));     \
    s = __fmaf_rn(__fadd_rn(e1, f1), DEQ, c2v.y); MIN2(P1, P2, PACKV(s, col + 1)); \
    s = __fmaf_rn(__fadd_rn(e2, f2), DEQ, c2v.x); MIN2(Q1, Q2, PACKV(s, col));     \
    s = __fmaf_rn(__fadd_rn(e3, f3), DEQ, c2v.y); MIN2(Q1, Q2, PACKV(s, col + 1)); \
} while (0)

// ---------------- main: SINGLE-pass fp16 HMMA scan, 2 m-tiles/warp, packed min-2 ----------------
__global__ __launch_bounds__(THREADS, 1)
void vq_main(const float* __restrict__ residual,
             const float* __restrict__ cb,
             float* __restrict__ qout,
             float* __restrict__ codes,
             int N, int K, int wq, int wc)
{
    extern __shared__ __align__(16) unsigned char dsm[];
    const uint32_t sb = smem_u32(dsm);

    float*        sC2  = (float*)(dsm + OFF_C2);
    float*        sC2B = (float*)(dsm + OFF_C2B);
    float*        sR2  = (float*)(dsm + OFF_R2);
    unsigned int* sM1  = (unsigned int*)(dsm + OFF_M1);
    unsigned int* sM2  = (unsigned int*)(dsm + OFF_M2);
    int*          sFlag= (int*)(dsm + OFF_FLAG);
    int*          sNF  = (int*)(dsm + OFF_NF);

    const int tid  = threadIdx.x;
    const int lane = tid & 31;
    const int warp = tid >> 5;
    const int m0   = blockIdx.x * TM;
    const int rows = (N - m0 < TM) ? (N - m0) : TM;
    const int NT   = K >> 3;

    if (tid == 0) *sNF = 0;
    for (int i = tid; i < K; i += THREADS) {
        float c2 = g_c2[i];
        sC2[i]  = c2;
        sC2B[i] = c2 + BIAS;
    }

    // --- per-row: residual -> fp16 swizzled smem + exact r2 (R1 pattern) ---
    {
        const int r = tid;
        unsigned int* aU = reinterpret_cast<unsigned int*>(dsm + OFF_A) + r * 32;
        float r2 = 0.f;
        if (r < rows) {
            const float4* rr = reinterpret_cast<const float4*>(residual + (size_t)(m0 + r) * DIM);
            float p0 = 0.f, p1 = 0.f, p2 = 0.f, p3 = 0.f;
#pragma unroll
            for (int j = 0; j < 16; j++) {
                float4 v = rr[j];
                p0 += v.x * v.x;
                p1 += v.y * v.y;
                p2 += v.z * v.z;
                p3 += v.w * v.w;
                __half2 h0 = __floats2half2_rn(v.x, v.y);
                __half2 h1 = __floats2half2_rn(v.z, v.w);
                int j0 = 2 * j, j1 = 2 * j + 1;
                aU[(((j0 >> 2) ^ (r & 7)) << 2) + (j0 & 3)] = *reinterpret_cast<unsigned int*>(&h0);
                aU[(((j1 >> 2) ^ (r & 7)) << 2) + (j1 & 3)] = *reinterpret_cast<unsigned int*>(&h1);
            }
            r2 = (p0 + p1) + (p2 + p3);
        } else {
#pragma unroll
            for (int j = 0; j < 32; j++) aU[j] = 0;
        }
        sR2[r] = r2;
    }
    __syncthreads();

    // --- A fragments (resident): 2 m-tiles x 4 k-chunks, swizzled ldmatrix.x4 ---
    uint32_t a[2][4][4];
#pragma unroll
    for (int mt = 0; mt < 2; mt++) {
        const uint32_t rowb = (uint32_t)(warp * 32 + mt * 16 + (lane & 15)) * 128u;
#pragma unroll
        for (int kc = 0; kc < 4; kc++) {
            uint32_t phys = (uint32_t)((2 * kc + (lane >> 4)) ^ (lane & 7));
            uint32_t ad = sb + OFF_A + rowb + (phys << 4);
            asm volatile("ldmatrix.sync.aligned.m8n8.x4.shared.b16 {%0,%1,%2,%3}, [%4];"
                : "=r"(a[mt][kc][0]), "=r"(a[mt][kc][1]),
                  "=r"(a[mt][kc][2]), "=r"(a[mt][kc][3])
                : "r"(ad));
        }
    }

    const uint4* bp = g_cbFrag + lane;          // per-lane fragment stream
    const float* c2Bp = sC2B + ((lane & 3) << 1);
    const int rA0 = warp * 32 + (lane >> 2);    // slot rows: rA0, +8, +16, +24
    const unsigned int lcb = (unsigned int)((lane & 3) << 1);

    // ================= single pass: packed min-2 of s_b = (c2+BIAS) - 2*dot~ =================
    unsigned int A1 = 0xFFFFFFFFu, A2 = 0xFFFFFFFFu;  // rA0
    unsigned int B1 = 0xFFFFFFFFu, B2 = 0xFFFFFFFFu;  // rA0+8
    unsigned int C1 = 0xFFFFFFFFu, C2 = 0xFFFFFFFFu;  // rA0+16
    unsigned int D1 = 0xFFFFFFFFu, D2 = 0xFFFFFFFFu;  // rA0+24

    {
        uint4 c0 = bp[0], c1 = bp[32];
#pragma unroll 1
        for (int nt = 0; nt < NT; nt++) {
            const int ntn = (nt + 1 < NT) ? nt + 1 : nt;
            uint4 n0 = bp[ntn * 64], n1 = bp[ntn * 64 + 32];
            const float2 c2v = *reinterpret_cast<const float2*>(c2Bp + (nt << 3));
            const unsigned int col = (unsigned int)(nt << 3) + lcb;
            MT_STEP(a[0], A1, A2, B1, B2);
            MT_STEP(a[1], C1, C2, D1, D2);
            c0 = n0; c1 = n1;
        }
    }

    // --- quad-merge min-2 across the 4 lanes covering each row ---
#pragma unroll
    for (int st = 1; st <= 2; st <<= 1) {
        unsigned int o1, o2;
        o1 = __shfl_xor_sync(0xFFFFFFFFu, A1, st);
        o2 = __shfl_xor_sync(0xFFFFFFFFu, A2, st);
        MERGE2(A1, A2, o1, o2);
        o1 = __shfl_xor_sync(0xFFFFFFFFu, B1, st);
        o2 = __shfl_xor_sync(0xFFFFFFFFu, B2, st);
        MERGE2(B1, B2, o1, o2);
        o1 = __shfl_xor_sync(0xFFFFFFFFu, C1, st);
        o2 = __shfl_xor_sync(0xFFFFFFFFu, C2, st);
        MERGE2(C1, C2, o1, o2);
        o1 = __shfl_xor_sync(0xFFFFFFFFu, D1, st);
        o2 = __shfl_xor_sync(0xFFFFFFFFu, D2, st);
        MERGE2(D1, D2, o1, o2);
    }
    if ((lane & 3) == 0) {
        sM1[rA0]      = A1; sM2[rA0]      = A2;
        sM1[rA0 + 8]  = B1; sM2[rA0 + 8]  = B2;
        sM1[rA0 + 16] = C1; sM2[rA0 + 16] = C2;
        sM1[rA0 + 24] = D1; sM2[rA0 + 24] = D2;
    }
    __syncthreads();

    // ================= per-row decision =================
    const float CmaxC = __uint_as_float(g_cmaxU) * 0.00390625f;   // Cmax * 2^-8
    const int t = tid;
    if (t < rows) {
        const unsigned int u1 = sM1[t], u2 = sM2[t];
        const float f1 = __uint_as_float(u1 & 0xFFFFFC00u);
        const float f2 = __uint_as_float(u2 & 0xFFFFFC00u);
        const float r2 = sR2[t];
        const float th = sqrtf(r2) * CmaxC + 1e-4f;
        if (f2 - f1 > th) {
            const int bestK = (int)(u1 & 1023u);      // unique in window => argmin
            const int n = m0 + t;
            if (wc) codes[n] = (float)bestK;
            if (wq) {
                const float4* brow = reinterpret_cast<const float4*>(cb + (size_t)bestK * DIM);
                float4* qo = reinterpret_cast<float4*>(qout + (size_t)n * DIM);
#pragma unroll
                for (int j = 0; j < 16; j++) qo[j] = brow[j];
            }
        } else {
            int idx = atomicAdd(sNF, 1);
            sFlag[idx] = t;
        }
    }
    __syncthreads();

    // ================= cooperative exact rescan for flagged rows (R1-proven math) =================
    const int nf = *sNF;
    for (int i = warp; i < nf; i += 16) {
        const int row = sFlag[i];
        const int n = m0 + row;
        const float r2 = sR2[row];
        float r[DIM];
        {
            const float4* rr = reinterpret_cast<const float4*>(residual + (size_t)n * DIM);
#pragma unroll
            for (int j = 0; j < 16; j++) {
                float4 v = rr[j];
                r[4 * j + 0] = v.x; r[4 * j + 1] = v.y;
                r[4 * j + 2] = v.z; r[4 * j + 3] = v.w;
            }
        }
        float best = 3.402823466e+38f;
        int bestK = 0x7FFFFFFF;
        for (int k = lane; k < K; k += 32) {
            const float4* c4 = reinterpret_cast<const float4*>(cb + (size_t)k * DIM);
            float a0 = 0.f;
#pragma unroll
            for (int j = 0; j < 16; j++) {
                float4 v = c4[j];
                a0 += r[4 * j + 0] * v.x;
                a0 += r[4 * j + 1] * v.y;
                a0 += r[4 * j + 2] * v.z;
                a0 += r[4 * j + 3] * v.w;
            }
            float d = (r2 + sC2[k]) - 2.0f * a0;
            if (d < best || (d == best && k < bestK)) { best = d; bestK = k; }
        }
#pragma unroll
        for (int off = 16; off >= 1; off >>= 1) {
            float ob = __shfl_xor_sync(0xFFFFFFFFu, best, off);
            int   ok = __shfl_xor_sync(0xFFFFFFFFu, bestK, off);
            if (ob < best || (ob == best && ok < bestK)) { best = ob; bestK = ok; }
        }
        if (wc && lane == 0) codes[n] = (float)bestK;
        if (wq && lane < 16) {
            const float4* brow = reinterpret_cast<const float4*>(cb + (size_t)bestK * DIM);
            reinterpret_cast<float4*>(qout + (size_t)n * DIM)[lane] = brow[lane];
        }
    }
}

// ---------------- launch ----------------
extern "C" void kernel_launch(void* const* d_in, const int* in_sizes, int n_in,
                              void* d_out, int out_size)
{
    const float* residual = (const float*)d_in[0];
    const float* cb       = (const float*)d_in[1];
    const int N = in_sizes[0] / DIM;
    const int K = in_sizes[1] / DIM;

    float* out = (float*)d_out;
    int write_q = 0, write_codes = 0;
    float* qout = out;
    float* codes = out;
    if (out_size >= N * DIM + N) {
        write_q = 1; write_codes = 1;
        codes = out + (size_t)N * DIM;
    } else if (out_size >= N * DIM) {
        write_q = 1;
    } else {
        write_codes = 1;
    }

    cudaFuncSetAttribute(vq_main, cudaFuncAttributeMaxDynamicSharedMemorySize, SMEM_DYN);

    prep_kernel<<<(K + 255) / 256, 256>>>(cb, K);

    int blocks = (N + TM - 1) / TM;
    vq_main<<<blocks, THREADS, SMEM_DYN>>>(residual, cb, qout, codes,
                                           N, K, write_q, write_codes);
}

// round 15
// speedup vs baseline: 1.0543x; 1.0543x over previous
#include <cuda_runtime.h>
#include <cuda_fp16.h>
#include <cstdint>

#define DIM     64
#define KMAX    1024
#define TM      256          // rows per CTA
#define THREADS 512          // 16 warps x 1 m-tile = 16 rows per warp

// ---------------- device globals (prep results) ----------------
__device__ float g_c2[KMAX];
__device__ unsigned int g_cmaxU;   // asuint(max ||c_k||), positive-float monotone
// fragment-ordered fp16 (x512) codebook image: for each n-tile (8 codes) the exact
// 8 B-fragment regs x 32 lanes the MMA needs. uint4 index = nt*64 + half*32 + lane.
__device__ __align__(16) uint4 g_cbFrag[(KMAX / 8) * 64];

// ---------------- smem layout (byte offsets) ----------------
#define OFF_A     0          // 256*128 = 32768 (fp16 swizzled A staging)
#define OFF_C2    32768      // 4096   (raw c2, exact phase)
#define OFF_C2B   36864      // 4096   (c2 + 0.25 bias, scan phase)
#define OFF_R2    40960      // 1024
#define OFF_M1    41984      // 1024
#define OFF_M2    43008      // 1024
#define OFF_FLAG  44032      // 1024
#define OFF_NF    45056      // 16
#define SMEM_DYN  45072

#define BIAS 0.25f
#define DEQ  (-0.00390625f)   // -2^-8 : undoes B x512 and applies the -2 factor

__device__ __forceinline__ uint32_t smem_u32(const void* p) {
    uint32_t a;
    asm("{ .reg .u64 t; cvta.to.shared.u64 t, %1; cvt.u32.u64 %0, t; }"
        : "=r"(a) : "l"(p));
    return a;
}

// ---------------- prep: c2 (R1-exact) + fp16 fragment codebook (x512) + Cmax ----------------
__global__ void prep_kernel(const float* __restrict__ cb, int K) {
    int k = blockIdx.x * blockDim.x + threadIdx.x;
    if (k >= K) return;
    const float4* row = reinterpret_cast<const float4*>(cb + (size_t)k * DIM);
    float vals[DIM];
    float p0 = 0.f, p1 = 0.f, p2 = 0.f, p3 = 0.f;
#pragma unroll
    for (int j = 0; j < 16; j += 4) {
        float4 a = row[j + 0];
        float4 b = row[j + 1];
        float4 c = row[j + 2];
        float4 d = row[j + 3];
        p0 += a.x * a.x + a.y * a.y + a.z * a.z + a.w * a.w;
        p1 += b.x * b.x + b.y * b.y + b.z * b.z + b.w * b.w;
        p2 += c.x * c.x + c.y * c.y + c.z * c.z + c.w * c.w;
        p3 += d.x * d.x + d.y * d.y + d.z * d.z + d.w * d.w;
        vals[4*(j+0)+0]=a.x; vals[4*(j+0)+1]=a.y; vals[4*(j+0)+2]=a.z; vals[4*(j+0)+3]=a.w;
        vals[4*(j+1)+0]=b.x; vals[4*(j+1)+1]=b.y; vals[4*(j+1)+2]=b.z; vals[4*(j+1)+3]=b.w;
        vals[4*(j+2)+0]=c.x; vals[4*(j+2)+1]=c.y; vals[4*(j+2)+2]=c.z; vals[4*(j+2)+3]=c.w;
        vals[4*(j+3)+0]=d.x; vals[4*(j+3)+1]=d.y; vals[4*(j+3)+2]=d.z; vals[4*(j+3)+3]=d.w;
    }
    float c2 = (p0 + p1) + (p2 + p3);
    g_c2[k] = c2;
    atomicMax(&g_cmaxU, __float_as_uint(sqrtf(c2)));

    // Fragment image: lane l=4*i+q (i = code-in-tile) receives in b-reg j the fp16
    // pair (k-dims 8j+2q, 8j+2q+1), scaled x512.
    const int nt = k >> 3, i = k & 7;
    unsigned int* frag = reinterpret_cast<unsigned int*>(g_cbFrag) + nt * 256;
#pragma unroll
    for (int j = 0; j < 8; j++) {
#pragma unroll
        for (int q = 0; q < 4; q++) {
            __half2 pr = __floats2half2_rn(vals[8 * j + 2 * q]     * 512.0f,
                                           vals[8 * j + 2 * q + 1] * 512.0f);
            frag[(j >> 2) * 128 + (4 * i + q) * 4 + (j & 3)] =
                *reinterpret_cast<unsigned int*>(&pr);
        }
    }
}

// ---------------- inner-step macros ----------------
#define MMAF16(d0, d1, d2, d3, a0r, a1r, a2r, a3r, b0r, b1r)                       \
    asm volatile(                                                                  \
        "mma.sync.aligned.m16n8k16.row.col.f32.f16.f16.f32 "                       \
        "{%0,%1,%2,%3}, {%4,%5,%6,%7}, {%8,%9}, {%0,%1,%2,%3};"                    \
        : "+f"(d0), "+f"(d1), "+f"(d2), "+f"(d3)                                   \
        : "r"(a0r), "r"(a1r), "r"(a2r), "r"(a3r), "r"(b0r), "r"(b1r))

// insert packed value v into sorted pair (M1x,M2x)
#define MIN2(M1x, M2x, v) do {                                                     \
    unsigned int t1 = umax(M1x, (v));                                              \
    M1x = umin(M1x, (v));                                                          \
    M2x = umin(M2x, t1);                                                           \
} while (0)

// merge other sorted pair (o1<=o2) into (M1x,M2x)
#define MERGE2(M1x, M2x, o1, o2) do {                                              \
    unsigned int hi = umax(M1x, (o1));                                             \
    M1x = umin(M1x, (o1));                                                         \
    M2x = umin(hi, umin(M2x, (o2)));                                               \
} while (0)

#define PACKV(sv, col) ((__float_as_uint(sv) & 0xFFFFFC00u) | (unsigned int)(col))

// ---------------- main: SINGLE-pass fp16 HMMA scan, 1 m-tile/warp, packed min-2 ----------------
__global__ __launch_bounds__(THREADS, 1)
void vq_main(const float* __restrict__ residual,
             const float* __restrict__ cb,
             float* __restrict__ qout,
             float* __restrict__ codes,
             int N, int K, int wq, int wc)
{
    extern __shared__ __align__(16) unsigned char dsm[];
    const uint32_t sb = smem_u32(dsm);

    float*        sC2  = (float*)(dsm + OFF_C2);
    float*        sC2B = (float*)(dsm + OFF_C2B);
    float*        sR2  = (float*)(dsm + OFF_R2);
    unsigned int* sM1  = (unsigned int*)(dsm + OFF_M1);
    unsigned int* sM2  = (unsigned int*)(dsm + OFF_M2);
    int*          sFlag= (int*)(dsm + OFF_FLAG);
    int*          sNF  = (int*)(dsm + OFF_NF);

    const int tid  = threadIdx.x;
    const int lane = tid & 31;
    const int warp = tid >> 5;
    const int m0   = blockIdx.x * TM;
    const int rows = (N - m0 < TM) ? (N - m0) : TM;
    const int NT   = K >> 3;

    if (tid == 0) *sNF = 0;
    for (int i = tid; i < K; i += THREADS) {
        float c2 = g_c2[i];
        sC2[i]  = c2;
        sC2B[i] = c2 + BIAS;
    }

    // --- per-row: residual -> fp16 swizzled smem + exact r2 (R1 pattern) ---
    if (tid < TM) {
        const int r = tid;
        unsigned int* aU = reinterpret_cast<unsigned int*>(dsm + OFF_A) + r * 32;
        float r2 = 0.f;
        if (r < rows) {
            const float4* rr = reinterpret_cast<const float4*>(residual + (size_t)(m0 + r) * DIM);
            float p0 = 0.f, p1 = 0.f, p2 = 0.f, p3 = 0.f;
#pragma unroll
            for (int j = 0; j < 16; j++) {
                float4 v = rr[j];
                p0 += v.x * v.x;
                p1 += v.y * v.y;
                p2 += v.z * v.z;
                p3 += v.w * v.w;
                __half2 h0 = __floats2half2_rn(v.x, v.y);
                __half2 h1 = __floats2half2_rn(v.z, v.w);
                int j0 = 2 * j, j1 = 2 * j + 1;
                aU[(((j0 >> 2) ^ (r & 7)) << 2) + (j0 & 3)] = *reinterpret_cast<unsigned int*>(&h0);
                aU[(((j1 >> 2) ^ (r & 7)) << 2) + (j1 & 3)] = *reinterpret_cast<unsigned int*>(&h1);
            }
            r2 = (p0 + p1) + (p2 + p3);
        } else {
#pragma unroll
            for (int j = 0; j < 32; j++) aU[j] = 0;
        }
        sR2[r] = r2;
    }
    __syncthreads();

    // --- A fragments (resident): 1 m-tile x 4 k-chunks as SCALARS (demotion-proof) ---
    uint32_t a00, a01, a02, a03, a10, a11, a12, a13;
    uint32_t a20, a21, a22, a23, a30, a31, a32, a33;
    {
        const uint32_t rowb = (uint32_t)(warp * 16 + (lane & 15)) * 128u;
        uint32_t phys, ad;
        phys = (uint32_t)((0 + (lane >> 4)) ^ (lane & 7));
        ad = sb + OFF_A + rowb + (phys << 4);
        asm volatile("ldmatrix.sync.aligned.m8n8.x4.shared.b16 {%0,%1,%2,%3}, [%4];"
            : "=r"(a00), "=r"(a01), "=r"(a02), "=r"(a03) : "r"(ad));
        phys = (uint32_t)((2 + (lane >> 4)) ^ (lane & 7));
        ad = sb + OFF_A + rowb + (phys << 4);
        asm volatile("ldmatrix.sync.aligned.m8n8.x4.shared.b16 {%0,%1,%2,%3}, [%4];"
            : "=r"(a10), "=r"(a11), "=r"(a12), "=r"(a13) : "r"(ad));
        phys = (uint32_t)((4 + (lane >> 4)) ^ (lane & 7));
        ad = sb + OFF_A + rowb + (phys << 4);
        asm volatile("ldmatrix.sync.aligned.m8n8.x4.shared.b16 {%0,%1,%2,%3}, [%4];"
            : "=r"(a20), "=r"(a21), "=r"(a22), "=r"(a23) : "r"(ad));
        phys = (uint32_t)((6 + (lane >> 4)) ^ (lane & 7));
        ad = sb + OFF_A + rowb + (phys << 4);
        asm volatile("ldmatrix.sync.aligned.m8n8.x4.shared.b16 {%0,%1,%2,%3}, [%4];"
            : "=r"(a30), "=r"(a31), "=r"(a32), "=r"(a33) : "r"(ad));
    }

    const uint4* bp = g_cbFrag + lane;          // per-lane fragment stream
    const float* c2Bp = sC2B + ((lane & 3) << 1);
    const int rA0 = warp * 16 + (lane >> 2);    // slot rows: rA0 and rA0+8
    const unsigned int lcb = (unsigned int)((lane & 3) << 1);

    // ================= single pass: packed min-2 of s_b = (c2+BIAS) - 2^-8*dot' =================
    unsigned int A1 = 0xFFFFFFFFu, A2 = 0xFFFFFFFFu;  // row rA0
    unsigned int B1 = 0xFFFFFFFFu, B2 = 0xFFFFFFFFu;  // row rA0+8

    {
        uint4 c0 = bp[0], c1 = bp[32];
#pragma unroll 1
        for (int nt = 0; nt < NT; nt++) {
            const int ntn = (nt + 1 < NT) ? nt + 1 : nt;
            uint4 n0 = bp[ntn * 64], n1 = bp[ntn * 64 + 32];
            const float2 c2v = *reinterpret_cast<const float2*>(c2Bp + (nt << 3));
            const unsigned int col = (unsigned int)(nt << 3) + lcb;
            float e0 = 0.f, e1 = 0.f, e2 = 0.f, e3 = 0.f;
            float f0 = 0.f, f1 = 0.f, f2 = 0.f, f3 = 0.f;
            MMAF16(e0, e1, e2, e3, a00, a01, a02, a03, c0.x, c0.y);
            MMAF16(f0, f1, f2, f3, a20, a21, a22, a23, c1.x, c1.y);
            MMAF16(e0, e1, e2, e3, a10, a11, a12, a13, c0.z, c0.w);
            MMAF16(f0, f1, f2, f3, a30, a31, a32, a33, c1.z, c1.w);
            float s;
            s = __fmaf_rn(__fadd_rn(e0, f0), DEQ, c2v.x); MIN2(A1, A2, PACKV(s, col));
            s = __fmaf_rn(__fadd_rn(e1, f1), DEQ, c2v.y); MIN2(A1, A2, PACKV(s, col + 1));
            s = __fmaf_rn(__fadd_rn(e2, f2), DEQ, c2v.x); MIN2(B1, B2, PACKV(s, col));
            s = __fmaf_rn(__fadd_rn(e3, f3), DEQ, c2v.y); MIN2(B1, B2, PACKV(s, col + 1));
            c0 = n0; c1 = n1;
        }
    }

    // --- quad-merge min-2 across the 4 lanes covering each row ---
#pragma unroll
    for (int st = 1; st <= 2; st <<= 1) {
        unsigned int o1, o2;
        o1 = __shfl_xor_sync(0xFFFFFFFFu, A1, st);
        o2 = __shfl_xor_sync(0xFFFFFFFFu, A2, st);
        MERGE2(A1, A2, o1, o2);
        o1 = __shfl_xor_sync(0xFFFFFFFFu, B1, st);
        o2 = __shfl_xor_sync(0xFFFFFFFFu, B2, st);
        MERGE2(B1, B2, o1, o2);
    }
    if ((lane & 3) == 0) {
        sM1[rA0]     = A1; sM2[rA0]     = A2;
        sM1[rA0 + 8] = B1; sM2[rA0 + 8] = B2;
    }
    __syncthreads();

    // ================= per-row decision =================
    const float CmaxC = __uint_as_float(g_cmaxU) * 0.00390625f;   // Cmax * 2^-8
    const int t = tid;
    if (t < rows) {
        const unsigned int u1 = sM1[t], u2 = sM2[t];
        const float f1 = __uint_as_float(u1 & 0xFFFFFC00u);
        const float f2 = __uint_as_float(u2 & 0xFFFFFC00u);
        const float r2 = sR2[t];
        const float th = sqrtf(r2) * CmaxC + 1e-4f;
        if (f2 - f1 > th) {
            const int bestK = (int)(u1 & 1023u);      // unique in window => argmin
            const int n = m0 + t;
            if (wc) codes[n] = (float)bestK;
            if (wq) {
                const float4* brow = reinterpret_cast<const float4*>(cb + (size_t)bestK * DIM);
                float4* qo = reinterpret_cast<float4*>(qout + (size_t)n * DIM);
#pragma unroll
                for (int j = 0; j < 16; j++) qo[j] = brow[j];
            }
        } else {
            int idx = atomicAdd(sNF, 1);
            sFlag[idx] = t;
        }
    }
    __syncthreads();

    // ================= cooperative exact rescan for flagged rows (R1-proven math) =================
    const int nf = *sNF;
    for (int i = warp; i < nf; i += 16) {
        const int row = sFlag[i];
        const int n = m0 + row;
        const float r2 = sR2[row];
        float r[DIM];
        {
            const float4* rr = reinterpret_cast<const float4*>(residual + (size_t)n * DIM);
#pragma unroll
            for (int j = 0; j < 16; j++) {
                float4 v = rr[j];
                r[4 * j + 0] = v.x; r[4 * j + 1] = v.y;
                r[4 * j + 2] = v.z; r[4 * j + 3] = v.w;
            }
        }
        float best = 3.402823466e+38f;
        int bestK = 0x7FFFFFFF;
        for (int k = lane; k < K; k += 32) {
            const float4* c4 = reinterpret_cast<const float4*>(cb + (size_t)k * DIM);
            float a0 = 0.f;
#pragma unroll
            for (int j = 0; j < 16; j++) {
                float4 v = c4[j];
                a0 += r[4 * j + 0] * v.x;
                a0 += r[4 * j + 1] * v.y;
                a0 += r[4 * j + 2] * v.z;
                a0 += r[4 * j + 3] * v.w;
            }
            float d = (r2 + sC2[k]) - 2.0f * a0;
            if (d < best || (d == best && k < bestK)) { best = d; bestK = k; }
        }
#pragma unroll
        for (int off = 16; off >= 1; off >>= 1) {
            float ob = __shfl_xor_sync(0xFFFFFFFFu, best, off);
            int   ok = __shfl_xor_sync(0xFFFFFFFFu, bestK, off);
            if (ob < best || (ob == best && ok < bestK)) { best = ob; bestK = ok; }
        }
        if (wc && lane == 0) codes[n] = (float)bestK;
        if (wq && lane < 16) {
            const float4* brow = reinterpret_cast<const float4*>(cb + (size_t)bestK * DIM);
            reinterpret_cast<float4*>(qout + (size_t)n * DIM)[lane] = brow[lane];
        }
    }
}

// ---------------- launch ----------------
extern "C" void kernel_launch(void* const* d_in, const int* in_sizes, int n_in,
                              void* d_out, int out_size)
{
    const float* residual = (const float*)d_in[0];
    const float* cb       = (const float*)d_in[1];
    const int N = in_sizes[0] / DIM;
    const int K = in_sizes[1] / DIM;

    float* out = (float*)d_out;
    int write_q = 0, write_codes = 0;
    float* qout = out;
    float* codes = out;
    if (out_size >= N * DIM + N) {
        write_q = 1; write_codes = 1;
        codes = out + (size_t)N * DIM;
    } else if (out_size >= N * DIM) {
        write_q = 1;
    } else {
        write_codes = 1;
    }

    cudaFuncSetAttribute(vq_main, cudaFuncAttributeMaxDynamicSharedMemorySize, SMEM_DYN);

    prep_kernel<<<(K + 255) / 256, 256>>>(cb, K);

    int blocks = (N + TM - 1) / TM;
    vq_main<<<blocks, THREADS, SMEM_DYN>>>(residual, cb, qout, codes,
                                           N, K, write_q, write_codes);
}

// round 16
// speedup vs baseline: 1.8656x; 1.7695x over previous
#include <cuda_runtime.h>
#include <cuda_bf16.h>
#include <cstdint>

#define DIM     64
#define KMAX    1024
#define TM      256          // rows per CTA
#define THREADS 512          // 16 warps, 1 m-tile (16 rows) each

// ---------------- device globals (prep results) ----------------
__device__ float g_c2[KMAX];
__device__ unsigned int g_cmaxU;   // asuint(max ||c_k||), positive-float monotone
// fragment-ordered bf16 codebook image: for each n-tile (8 codes) the exact
// 8 B-fragment regs x 32 lanes the MMA needs. uint4 index = nt*64 + half*32 + lane.
__device__ __align__(16) uint4 g_cbFrag[(KMAX / 8) * 64];

// ---------------- smem layout (byte offsets) ----------------
#define OFF_A     0          // 256*128 = 32768 (bf16 swizzled A staging)
#define OFF_C2    32768      // 1024*4  =  4096
#define OFF_R2    36864      // 256*4   =  1024
#define OFF_TM    37888      // 128*256*4 = 131072  (per-tile mins, [nt][row] fp32)
#define SMEM_DYN  168960

__device__ __forceinline__ uint32_t smem_u32(const void* p) {
    uint32_t a;
    asm("{ .reg .u64 t; cvta.to.shared.u64 t, %1; cvt.u32.u64 %0, t; }"
        : "=r"(a) : "l"(p));
    return a;
}

// ---------------- prep: c2 (R1-exact) + fragment-ordered bf16 codebook + Cmax ----------------
__global__ void prep_kernel(const float* __restrict__ cb, int K) {
    int k = blockIdx.x * blockDim.x + threadIdx.x;
    if (k >= K) return;
    const float4* row = reinterpret_cast<const float4*>(cb + (size_t)k * DIM);
    float vals[DIM];
    float p0 = 0.f, p1 = 0.f, p2 = 0.f, p3 = 0.f;
#pragma unroll
    for (int j = 0; j < 16; j += 4) {
        float4 a = row[j + 0];
        float4 b = row[j + 1];
        float4 c = row[j + 2];
        float4 d = row[j + 3];
        p0 += a.x * a.x + a.y * a.y + a.z * a.z + a.w * a.w;
        p1 += b.x * b.x + b.y * b.y + b.z * b.z + b.w * b.w;
        p2 += c.x * c.x + c.y * c.y + c.z * c.z + c.w * c.w;
        p3 += d.x * d.x + d.y * d.y + d.z * d.z + d.w * d.w;
        vals[4*(j+0)+0]=a.x; vals[4*(j+0)+1]=a.y; vals[4*(j+0)+2]=a.z; vals[4*(j+0)+3]=a.w;
        vals[4*(j+1)+0]=b.x; vals[4*(j+1)+1]=b.y; vals[4*(j+1)+2]=b.z; vals[4*(j+1)+3]=b.w;
        vals[4*(j+2)+0]=c.x; vals[4*(j+2)+1]=c.y; vals[4*(j+2)+2]=c.z; vals[4*(j+2)+3]=c.w;
        vals[4*(j+3)+0]=d.x; vals[4*(j+3)+1]=d.y; vals[4*(j+3)+2]=d.z; vals[4*(j+3)+3]=d.w;
    }
    float c2 = (p0 + p1) + (p2 + p3);
    g_c2[k] = c2;
    atomicMax(&g_cmaxU, __float_as_uint(sqrtf(c2)));

    // Fragment image: lane l=4*i+q (i = code-in-tile) receives in b-reg j the bf16
    // pair (k-dims 8j+2q, 8j+2q+1). uint addr = nt*256 + (j>>2)*128 + l*4 + (j&3).
    const int nt = k >> 3, i = k & 7;
    unsigned int* frag = reinterpret_cast<unsigned int*>(g_cbFrag) + nt * 256;
#pragma unroll
    for (int j = 0; j < 8; j++) {
#pragma unroll
        for (int q = 0; q < 4; q++) {
            __nv_bfloat162 pr = __floats2bfloat162_rn(vals[8 * j + 2 * q],
                                                      vals[8 * j + 2 * q + 1]);
            frag[(j >> 2) * 128 + (4 * i + q) * 4 + (j & 3)] =
                *reinterpret_cast<unsigned int*>(&pr);
        }
    }
}

// ---------------- inner-step macros ----------------
#define MMA16816(d0, d1, d2, d3, ar, b0r, b1r)                                    \
    asm volatile(                                                                  \
        "mma.sync.aligned.m16n8k16.row.col.f32.bf16.bf16.f32 "                     \
        "{%0,%1,%2,%3}, {%4,%5,%6,%7}, {%8,%9}, {%0,%1,%2,%3};"                    \
        : "+f"(d0), "+f"(d1), "+f"(d2), "+f"(d3)                                   \
        : "r"((ar)[0]), "r"((ar)[1]), "r"((ar)[2]), "r"((ar)[3]),                  \
          "r"(b0r), "r"(b1r))

// ---------------- main: single MMA pass -> per-tile mins in smem -> exact recheck ----------------
__global__ __launch_bounds__(THREADS, 1)
void vq_main(const float* __restrict__ residual,
             const float* __restrict__ cb,
             float* __restrict__ qout,
             float* __restrict__ codes,
             int N, int K, int wq, int wc)
{
    extern __shared__ __align__(16) unsigned char dsm[];
    const uint32_t sb = smem_u32(dsm);

    float* sC2 = (float*)(dsm + OFF_C2);
    float* sR2 = (float*)(dsm + OFF_R2);
    float* sTM = (float*)(dsm + OFF_TM);   // [nt][row] : nt*TM + row

    const int tid  = threadIdx.x;
    const int lane = tid & 31;
    const int warp = tid >> 5;
    const int m0   = blockIdx.x * TM;
    const int rows = (N - m0 < TM) ? (N - m0) : TM;
    const int NT   = K >> 3;

    for (int i = tid; i < K; i += THREADS) sC2[i] = g_c2[i];

    // --- per-row: residual -> bf16 swizzled smem + exact r2 (R1 pattern) ---
    if (tid < TM) {
        const int r = tid;
        unsigned int* aU = reinterpret_cast<unsigned int*>(dsm + OFF_A) + r * 32;
        float r2 = 0.f;
        if (r < rows) {
            const float4* rr = reinterpret_cast<const float4*>(residual + (size_t)(m0 + r) * DIM);
            float p0 = 0.f, p1 = 0.f, p2 = 0.f, p3 = 0.f;
#pragma unroll
            for (int j = 0; j < 16; j++) {
                float4 v = rr[j];
                p0 += v.x * v.x;
                p1 += v.y * v.y;
                p2 += v.z * v.z;
                p3 += v.w * v.w;
                __nv_bfloat162 h0 = __floats2bfloat162_rn(v.x, v.y);
                __nv_bfloat162 h1 = __floats2bfloat162_rn(v.z, v.w);
                int j0 = 2 * j, j1 = 2 * j + 1;
                aU[(((j0 >> 2) ^ (r & 7)) << 2) + (j0 & 3)] = *reinterpret_cast<unsigned int*>(&h0);
                aU[(((j1 >> 2) ^ (r & 7)) << 2) + (j1 & 3)] = *reinterpret_cast<unsigned int*>(&h1);
            }
            r2 = (p0 + p1) + (p2 + p3);
        } else {
#pragma unroll
            for (int j = 0; j < 32; j++) aU[j] = 0;
        }
        sR2[r] = r2;
    }
    __syncthreads();

    // --- A fragments (resident): 1 m-tile x 4 k-chunks, swizzled ldmatrix.x4 (R9 form) ---
    uint32_t a[4][4];
    {
        const uint32_t rowb = (uint32_t)(warp * 16 + (lane & 15)) * 128u;
#pragma unroll
        for (int kc = 0; kc < 4; kc++) {
            uint32_t phys = (uint32_t)((2 * kc + (lane >> 4)) ^ (lane & 7));
            uint32_t ad = sb + OFF_A + rowb + (phys << 4);
            asm volatile("ldmatrix.sync.aligned.m8n8.x4.shared.b16 {%0,%1,%2,%3}, [%4];"
                : "=r"(a[kc][0]), "=r"(a[kc][1]), "=r"(a[kc][2]), "=r"(a[kc][3])
                : "r"(ad));
        }
    }

    const uint4* bp = g_cbFrag + lane;          // per-lane fragment stream
    const float* c2p = sC2 + ((lane & 3) << 1);
    const int rA0 = warp * 16 + (lane >> 2);    // slot rows: rA0 and rA0+8

    // ================= single MMA pass: per-tile mins of s~ = c2 - 2*dot~ =================
    {
        uint4 c0 = bp[0], c1 = bp[32];
        for (int nt = 0; nt < NT; nt++) {
            const int ntn = (nt + 1 < NT) ? nt + 1 : nt;
            uint4 n0 = bp[ntn * 64], n1 = bp[ntn * 64 + 32];
            const float2 c2v = *reinterpret_cast<const float2*>(c2p + (nt << 3));
            float e0 = 0.f, e1 = 0.f, e2 = 0.f, e3 = 0.f;
            float f0 = 0.f, f1 = 0.f, f2 = 0.f, f3 = 0.f;
            MMA16816(e0, e1, e2, e3, a[0], c0.x, c0.y);
            MMA16816(f0, f1, f2, f3, a[2], c1.x, c1.y);
            MMA16816(e0, e1, e2, e3, a[1], c0.z, c0.w);
            MMA16816(f0, f1, f2, f3, a[3], c1.z, c1.w);
            float s0 = __fmaf_rn(__fadd_rn(e0, f0), -2.0f, c2v.x);
            float s1 = __fmaf_rn(__fadd_rn(e1, f1), -2.0f, c2v.y);
            float s2 = __fmaf_rn(__fadd_rn(e2, f2), -2.0f, c2v.x);
            float s3 = __fmaf_rn(__fadd_rn(e3, f3), -2.0f, c2v.y);
            // quad-reduce to per-(row, tile) min
            float t0 = fminf(s0, s1);
            float t1 = fminf(s2, s3);
            t0 = fminf(t0, __shfl_xor_sync(0xFFFFFFFFu, t0, 1));
            t0 = fminf(t0, __shfl_xor_sync(0xFFFFFFFFu, t0, 2));
            t1 = fminf(t1, __shfl_xor_sync(0xFFFFFFFFu, t1, 1));
            t1 = fminf(t1, __shfl_xor_sync(0xFFFFFFFFu, t1, 2));
            if ((lane & 3) == 0) {
                sTM[nt * TM + rA0]     = t0;
                sTM[nt * TM + rA0 + 8] = t1;
            }
            c0 = n0; c1 = n1;
        }
    }
    __syncthreads();

    // ================= per-row: window over tile-mins -> exact fp32 recheck =================
    const float CmaxC = __uint_as_float(g_cmaxU) * 0.018f;
    const int t = tid;
    if (t < rows) {
        const float r2 = sR2[t];
        // rowmin over 128 tile-mins (conflict-free: stride TM floats)
        float rowmin = 3.402823466e+38f;
        for (int nt = 0; nt < NT; nt++) rowmin = fminf(rowmin, sTM[nt * TM + t]);
        const float lim = rowmin + (sqrtf(r2) * CmaxC + 5e-5f);

        // load residual row (R1 exact-phase pattern)
        float r[DIM];
        {
            const float4* rr = reinterpret_cast<const float4*>(residual + (size_t)(m0 + t) * DIM);
#pragma unroll
            for (int j = 0; j < 16; j++) {
                float4 v = rr[j];
                r[4 * j + 0] = v.x; r[4 * j + 1] = v.y;
                r[4 * j + 2] = v.z; r[4 * j + 3] = v.w;
            }
        }

        float best = 3.402823466e+38f;
        int bestK = 0x7FFFFFFF;
        for (int nt = 0; nt < NT; nt++) {
            if (sTM[nt * TM + t] <= lim) {
                // exact fp32 recheck of this tile's 8 codes (R1-proven math)
#pragma unroll 1
                for (int i = 0; i < 8; i++) {
                    const int k = nt * 8 + i;
                    const float4* c4 = reinterpret_cast<const float4*>(cb + (size_t)k * DIM);
                    float a0 = 0.f;
#pragma unroll
                    for (int j = 0; j < 16; j++) {
                        float4 v = c4[j];
                        a0 += r[4 * j + 0] * v.x;
                        a0 += r[4 * j + 1] * v.y;
                        a0 += r[4 * j + 2] * v.z;
                        a0 += r[4 * j + 3] * v.w;
                    }
                    float d = (r2 + sC2[k]) - 2.0f * a0;
                    if (d < best || (d == best && k < bestK)) { best = d; bestK = k; }
                }
            }
        }

        const int n = m0 + t;
        if (wc) codes[n] = (float)bestK;
        if (wq) {
            const float4* brow = reinterpret_cast<const float4*>(cb + (size_t)bestK * DIM);
            float4* qo = reinterpret_cast<float4*>(qout + (size_t)n * DIM);
#pragma unroll
            for (int j = 0; j < 16; j++) qo[j] = brow[j];
        }
    }
}

// ---------------- launch ----------------
extern "C" void kernel_launch(void* const* d_in, const int* in_sizes, int n_in,
                              void* d_out, int out_size)
{
    const float* residual = (const float*)d_in[0];
    const float* cb       = (const float*)d_in[1];
    const int N = in_sizes[0] / DIM;
    const int K = in_sizes[1] / DIM;

    float* out = (float*)d_out;
    int write_q = 0, write_codes = 0;
    float* qout = out;
    float* codes = out;
    if (out_size >= N * DIM + N) {
        write_q = 1; write_codes = 1;
        codes = out + (size_t)N * DIM;
    } else if (out_size >= N * DIM) {
        write_q = 1;
    } else {
        write_codes = 1;
    }

    cudaFuncSetAttribute(vq_main, cudaFuncAttributeMaxDynamicSharedMemorySize, SMEM_DYN);

    prep_kernel<<<(K + 255) / 256, 256>>>(cb, K);

    int blocks = (N + TM - 1) / TM;
    vq_main<<<blocks, THREADS, SMEM_DYN>>>(residual, cb, qout, codes,
                                           N, K, write_q, write_codes);
}

// round 17
// speedup vs baseline: 4.4692x; 2.3956x over previous
#include <cuda_runtime.h>
#include <cuda_bf16.h>
#include <cstdint>

#define DIM     64
#define KMAX    1024
#define TM      256          // rows per CTA
#define THREADS 512          // 16 warps, 1 m-tile (16 rows) each
#define CAPW    2048         // worklist capacity (entries)

// ---------------- device globals (prep results) ----------------
__device__ float g_c2[KMAX];
__device__ unsigned int g_cmaxU;   // asuint(max ||c_k||), positive-float monotone
// fragment-ordered bf16 codebook image: for each n-tile (8 codes) the exact
// 8 B-fragment regs x 32 lanes the MMA needs. uint4 index = nt*64 + half*32 + lane.
__device__ __align__(16) uint4 g_cbFrag[(KMAX / 8) * 64];

// ---------------- smem layout (byte offsets) ----------------
#define OFF_A     0          // 256*128 = 32768 (bf16 swizzled A staging)
#define OFF_C2    32768      // 1024*4  =  4096
#define OFF_R2    36864      // 256*4   =  1024
#define OFF_TM    37888      // 128*256*4 = 131072  (per-tile mins, [nt][row] fp32)
#define OFF_WL    168960     // 2048*4 = 8192 (worklist: row | nt<<16)
#define OFF_B64   177152     // 256*8 = 2048 (packed (enc(d)<<32)|k per row)
#define OFF_CNT   179200     // 16
#define SMEM_DYN  179216

__device__ __forceinline__ uint32_t smem_u32(const void* p) {
    uint32_t a;
    asm("{ .reg .u64 t; cvta.to.shared.u64 t, %1; cvt.u32.u64 %0, t; }"
        : "=r"(a) : "l"(p));
    return a;
}
// order-preserving float->uint (total order incl. negatives)
__device__ __forceinline__ unsigned int encf(float f) {
    unsigned int u = __float_as_uint(f);
    return (u & 0x80000000u) ? ~u : (u | 0x80000000u);
}

// ---------------- prep: c2 (R1-exact) + fragment-ordered bf16 codebook + Cmax ----------------
__global__ void prep_kernel(const float* __restrict__ cb, int K) {
    int k = blockIdx.x * blockDim.x + threadIdx.x;
    if (k >= K) return;
    const float4* row = reinterpret_cast<const float4*>(cb + (size_t)k * DIM);
    float vals[DIM];
    float p0 = 0.f, p1 = 0.f, p2 = 0.f, p3 = 0.f;
#pragma unroll
    for (int j = 0; j < 16; j += 4) {
        float4 a = row[j + 0];
        float4 b = row[j + 1];
        float4 c = row[j + 2];
        float4 d = row[j + 3];
        p0 += a.x * a.x + a.y * a.y + a.z * a.z + a.w * a.w;
        p1 += b.x * b.x + b.y * b.y + b.z * b.z + b.w * b.w;
        p2 += c.x * c.x + c.y * c.y + c.z * c.z + c.w * c.w;
        p3 += d.x * d.x + d.y * d.y + d.z * d.z + d.w * d.w;
        vals[4*(j+0)+0]=a.x; vals[4*(j+0)+1]=a.y; vals[4*(j+0)+2]=a.z; vals[4*(j+0)+3]=a.w;
        vals[4*(j+1)+0]=b.x; vals[4*(j+1)+1]=b.y; vals[4*(j+1)+2]=b.z; vals[4*(j+1)+3]=b.w;
        vals[4*(j+2)+0]=c.x; vals[4*(j+2)+1]=c.y; vals[4*(j+2)+2]=c.z; vals[4*(j+2)+3]=c.w;
        vals[4*(j+3)+0]=d.x; vals[4*(j+3)+1]=d.y; vals[4*(j+3)+2]=d.z; vals[4*(j+3)+3]=d.w;
    }
    float c2 = (p0 + p1) + (p2 + p3);
    g_c2[k] = c2;
    atomicMax(&g_cmaxU, __float_as_uint(sqrtf(c2)));

    // Fragment image: lane l=4*i+q (i = code-in-tile) receives in b-reg j the bf16
    // pair (k-dims 8j+2q, 8j+2q+1). uint addr = nt*256 + (j>>2)*128 + l*4 + (j&3).
    const int nt = k >> 3, i = k & 7;
    unsigned int* frag = reinterpret_cast<unsigned int*>(g_cbFrag) + nt * 256;
#pragma unroll
    for (int j = 0; j < 8; j++) {
#pragma unroll
        for (int q = 0; q < 4; q++) {
            __nv_bfloat162 pr = __floats2bfloat162_rn(vals[8 * j + 2 * q],
                                                      vals[8 * j + 2 * q + 1]);
            frag[(j >> 2) * 128 + (4 * i + q) * 4 + (j & 3)] =
                *reinterpret_cast<unsigned int*>(&pr);
        }
    }
}

// ---------------- inner-step macros ----------------
#define MMA16816(d0, d1, d2, d3, ar, b0r, b1r)                                    \
    asm volatile(                                                                  \
        "mma.sync.aligned.m16n8k16.row.col.f32.bf16.bf16.f32 "                     \
        "{%0,%1,%2,%3}, {%4,%5,%6,%7}, {%8,%9}, {%0,%1,%2,%3};"                    \
        : "+f"(d0), "+f"(d1), "+f"(d2), "+f"(d3)                                   \
        : "r"((ar)[0]), "r"((ar)[1]), "r"((ar)[2]), "r"((ar)[3]),                  \
          "r"(b0r), "r"(b1r))

// ---------------- main: single MMA pass -> tile mins -> compact worklist recheck ----------------
__global__ __launch_bounds__(THREADS, 1)
void vq_main(const float* __restrict__ residual,
             const float* __restrict__ cb,
             float* __restrict__ qout,
             float* __restrict__ codes,
             int N, int K, int wq, int wc)
{
    extern __shared__ __align__(16) unsigned char dsm[];
    const uint32_t sb = smem_u32(dsm);

    float*              sC2  = (float*)(dsm + OFF_C2);
    float*              sR2  = (float*)(dsm + OFF_R2);
    float*              sTM  = (float*)(dsm + OFF_TM);   // [nt][row]
    unsigned int*       sWL  = (unsigned int*)(dsm + OFF_WL);
    unsigned long long* sB64 = (unsigned long long*)(dsm + OFF_B64);
    int*                sCNT = (int*)(dsm + OFF_CNT);

    const int tid  = threadIdx.x;
    const int lane = tid & 31;
    const int warp = tid >> 5;
    const int m0   = blockIdx.x * TM;
    const int rows = (N - m0 < TM) ? (N - m0) : TM;
    const int NT   = K >> 3;

    if (tid == 0) *sCNT = 0;
    for (int i = tid; i < K; i += THREADS) sC2[i] = g_c2[i];

    // --- per-row: residual -> bf16 swizzled smem + exact r2 (R1 pattern) ---
    if (tid < TM) {
        const int r = tid;
        unsigned int* aU = reinterpret_cast<unsigned int*>(dsm + OFF_A) + r * 32;
        float r2 = 0.f;
        if (r < rows) {
            const float4* rr = reinterpret_cast<const float4*>(residual + (size_t)(m0 + r) * DIM);
            float p0 = 0.f, p1 = 0.f, p2 = 0.f, p3 = 0.f;
#pragma unroll
            for (int j = 0; j < 16; j++) {
                float4 v = rr[j];
                p0 += v.x * v.x;
                p1 += v.y * v.y;
                p2 += v.z * v.z;
                p3 += v.w * v.w;
                __nv_bfloat162 h0 = __floats2bfloat162_rn(v.x, v.y);
                __nv_bfloat162 h1 = __floats2bfloat162_rn(v.z, v.w);
                int j0 = 2 * j, j1 = 2 * j + 1;
                aU[(((j0 >> 2) ^ (r & 7)) << 2) + (j0 & 3)] = *reinterpret_cast<unsigned int*>(&h0);
                aU[(((j1 >> 2) ^ (r & 7)) << 2) + (j1 & 3)] = *reinterpret_cast<unsigned int*>(&h1);
            }
            r2 = (p0 + p1) + (p2 + p3);
        } else {
#pragma unroll
            for (int j = 0; j < 32; j++) aU[j] = 0;
        }
        sR2[r] = r2;
        sB64[r] = 0xFFFFFFFFFFFFFFFFull;
    }
    __syncthreads();

    // --- A fragments (resident): 1 m-tile x 4 k-chunks, swizzled ldmatrix.x4 ---
    uint32_t a[4][4];
    {
        const uint32_t rowb = (uint32_t)(warp * 16 + (lane & 15)) * 128u;
#pragma unroll
        for (int kc = 0; kc < 4; kc++) {
            uint32_t phys = (uint32_t)((2 * kc + (lane >> 4)) ^ (lane & 7));
            uint32_t ad = sb + OFF_A + rowb + (phys << 4);
            asm volatile("ldmatrix.sync.aligned.m8n8.x4.shared.b16 {%0,%1,%2,%3}, [%4];"
                : "=r"(a[kc][0]), "=r"(a[kc][1]), "=r"(a[kc][2]), "=r"(a[kc][3])
                : "r"(ad));
        }
    }

    const uint4* bp = g_cbFrag + lane;          // per-lane fragment stream
    const float* c2p = sC2 + ((lane & 3) << 1);
    const int rA0 = warp * 16 + (lane >> 2);    // slot rows: rA0 and rA0+8

    // ================= single MMA pass: per-tile mins of s~ = c2 - 2*dot~ =================
    {
        uint4 c0 = bp[0], c1 = bp[32];
        for (int nt = 0; nt < NT; nt++) {
            const int ntn = (nt + 1 < NT) ? nt + 1 : nt;
            uint4 n0 = bp[ntn * 64], n1 = bp[ntn * 64 + 32];
            const float2 c2v = *reinterpret_cast<const float2*>(c2p + (nt << 3));
            float e0 = 0.f, e1 = 0.f, e2 = 0.f, e3 = 0.f;
            float f0 = 0.f, f1 = 0.f, f2 = 0.f, f3 = 0.f;
            MMA16816(e0, e1, e2, e3, a[0], c0.x, c0.y);
            MMA16816(f0, f1, f2, f3, a[2], c1.x, c1.y);
            MMA16816(e0, e1, e2, e3, a[1], c0.z, c0.w);
            MMA16816(f0, f1, f2, f3, a[3], c1.z, c1.w);
            float s0 = __fmaf_rn(__fadd_rn(e0, f0), -2.0f, c2v.x);
            float s1 = __fmaf_rn(__fadd_rn(e1, f1), -2.0f, c2v.y);
            float s2 = __fmaf_rn(__fadd_rn(e2, f2), -2.0f, c2v.x);
            float s3 = __fmaf_rn(__fadd_rn(e3, f3), -2.0f, c2v.y);
            float t0 = fminf(s0, s1);
            float t1 = fminf(s2, s3);
            t0 = fminf(t0, __shfl_xor_sync(0xFFFFFFFFu, t0, 1));
            t0 = fminf(t0, __shfl_xor_sync(0xFFFFFFFFu, t0, 2));
            t1 = fminf(t1, __shfl_xor_sync(0xFFFFFFFFu, t1, 1));
            t1 = fminf(t1, __shfl_xor_sync(0xFFFFFFFFu, t1, 2));
            if ((lane & 3) == 0) {
                sTM[nt * TM + rA0]     = t0;
                sTM[nt * TM + rA0 + 8] = t1;
            }
            c0 = n0; c1 = n1;
        }
    }
    __syncthreads();

    // ================= phase 1: per-row window -> worklist of (row, tile) =================
    const float CmaxC = __uint_as_float(g_cmaxU) * 0.018f;
    if (tid < rows) {
        const int t = tid;
        float r0 = 3.0e38f, r1 = 3.0e38f, r2m = 3.0e38f, r3 = 3.0e38f;
        for (int nt = 0; nt < NT; nt += 4) {
            r0 = fminf(r0, sTM[(nt + 0) * TM + t]);
            r1 = fminf(r1, sTM[(nt + 1) * TM + t]);
            r2m = fminf(r2m, sTM[(nt + 2) * TM + t]);
            r3 = fminf(r3, sTM[(nt + 3) * TM + t]);
        }
        const float rowmin = fminf(fminf(r0, r1), fminf(r2m, r3));
        const float lim = rowmin + (sqrtf(sR2[t]) * CmaxC + 5e-5f);
        for (int nt = 0; nt < NT; nt++) {
            if (sTM[nt * TM + t] <= lim) {
                int idx = atomicAdd(sCNT, 1);
                if (idx < CAPW) sWL[idx] = (unsigned int)t | ((unsigned int)nt << 16);
            }
        }
    }
    __syncthreads();

    // ================= phase 2: one thread per entry, exact fp32 (R1 math), u64 atomicMin =================
    const int cnt = *sCNT;
    const int ncl = (cnt < CAPW) ? cnt : CAPW;
    for (int i = tid; i < ncl; i += THREADS) {
        const unsigned int e = sWL[i];
        const int row = (int)(e & 0xFFFFu);
        const int nt  = (int)(e >> 16);
        const float r2 = sR2[row];
        const float4* rr = reinterpret_cast<const float4*>(residual + (size_t)(m0 + row) * DIM);
        float acc[8];
#pragma unroll
        for (int c = 0; c < 8; c++) acc[c] = 0.f;
        const float4* cbp = reinterpret_cast<const float4*>(cb + (size_t)(nt * 8) * DIM);
#pragma unroll
        for (int j = 0; j < 16; j++) {
            float4 rv = rr[j];
#pragma unroll
            for (int c = 0; c < 8; c++) {
                float4 v = cbp[c * 16 + j];
                acc[c] += rv.x * v.x;
                acc[c] += rv.y * v.y;
                acc[c] += rv.z * v.z;
                acc[c] += rv.w * v.w;
            }
        }
        unsigned long long bestp = 0xFFFFFFFFFFFFFFFFull;
#pragma unroll
        for (int c = 0; c < 8; c++) {
            const int k = nt * 8 + c;
            float d = (r2 + sC2[k]) - 2.0f * acc[c];
            unsigned long long p = ((unsigned long long)encf(d) << 32) | (unsigned int)k;
            bestp = (p < bestp) ? p : bestp;
        }
        atomicMin(&sB64[row], bestp);
    }
    __syncthreads();

    // ================= phase 3: outputs (or overflow fallback) =================
    if (cnt <= CAPW) {
        if (tid < rows) {
            const int bestK = (int)(sB64[tid] & 0xFFFFFFFFull);
            const int n = m0 + tid;
            if (wc) codes[n] = (float)bestK;
            if (wq) {
                const float4* brow = reinterpret_cast<const float4*>(cb + (size_t)bestK * DIM);
                float4* qo = reinterpret_cast<float4*>(qout + (size_t)n * DIM);
#pragma unroll
                for (int j = 0; j < 16; j++) qo[j] = brow[j];
            }
        }
    } else {
        // overflow (statistically never): cooperative full exact rescan for all rows
        for (int i = warp; i < rows; i += 16) {
            const int n = m0 + i;
            const float r2 = sR2[i];
            float r[DIM];
            const float4* rr = reinterpret_cast<const float4*>(residual + (size_t)n * DIM);
#pragma unroll
            for (int j = 0; j < 16; j++) {
                float4 v = rr[j];
                r[4 * j + 0] = v.x; r[4 * j + 1] = v.y;
                r[4 * j + 2] = v.z; r[4 * j + 3] = v.w;
            }
            float best = 3.402823466e+38f;
            int bestK = 0x7FFFFFFF;
            for (int k = lane; k < K; k += 32) {
                const float4* c4 = reinterpret_cast<const float4*>(cb + (size_t)k * DIM);
                float a0 = 0.f;
#pragma unroll
                for (int j = 0; j < 16; j++) {
                    float4 v = c4[j];
                    a0 += r[4 * j + 0] * v.x;
                    a0 += r[4 * j + 1] * v.y;
                    a0 += r[4 * j + 2] * v.z;
                    a0 += r[4 * j + 3] * v.w;
                }
                float d = (r2 + sC2[k]) - 2.0f * a0;
                if (d < best || (d == best && k < bestK)) { best = d; bestK = k; }
            }
#pragma unroll
            for (int off = 16; off >= 1; off >>= 1) {
                float ob = __shfl_xor_sync(0xFFFFFFFFu, best, off);
                int   ok = __shfl_xor_sync(0xFFFFFFFFu, bestK, off);
                if (ob < best || (ob == best && ok < bestK)) { best = ob; bestK = ok; }
            }
            if (wc && lane == 0) codes[n] = (float)bestK;
            if (wq && lane < 16) {
                const float4* brow = reinterpret_cast<const float4*>(cb + (size_t)bestK * DIM);
                reinterpret_cast<float4*>(qout + (size_t)n * DIM)[lane] = brow[lane];
            }
        }
    }
}

// ---------------- launch ----------------
extern "C" void kernel_launch(void* const* d_in, const int* in_sizes, int n_in,
                              void* d_out, int out_size)
{
    const float* residual = (const float*)d_in[0];
    const float* cb       = (const float*)d_in[1];
    const int N = in_sizes[0] / DIM;
    const int K = in_sizes[1] / DIM;

    float* out = (float*)d_out;
    int write_q = 0, write_codes = 0;
    float* qout = out;
    float* codes = out;
    if (out_size >= N * DIM + N) {
        write_q = 1; write_codes = 1;
        codes = out + (size_t)N * DIM;
    } else if (out_size >= N * DIM) {
        write_q = 1;
    } else {
        write_codes = 1;
    }

    cudaFuncSetAttribute(vq_main, cudaFuncAttributeMaxDynamicSharedMemorySize, SMEM_DYN);

    prep_kernel<<<(K + 255) / 256, 256>>>(cb, K);

    int blocks = (N + TM - 1) / TM;
    vq_main<<<blocks, THREADS, SMEM_DYN>>>(residual, cb, qout, codes,
                                           N, K, write_q, write_codes);
}